// round 2
// baseline (speedup 1.0000x reference)
#include <cuda_runtime.h>
#include <cuda_bf16.h>

// GCN 2-layer: x[100000,128] @ W1[128,16] -> aggregate -> relu -> @ W2[16,4]
// -> aggregate -> log_softmax.  Edges: int32 [2, 3200000] (JAX x64 disabled:
// requested int64 silently becomes int32).

#define N_MAX 100000
#define E_MAX 3200000
#define F1 16
#define F2 4

// Scratch (static __device__ — no allocation allowed)
__device__ int    g_src[E_MAX];
__device__ int    g_dst[E_MAX];
__device__ float  g_norm[E_MAX];
__device__ float  g_dinv[N_MAX];
__device__ int    g_deg[N_MAX];
__device__ float4 g_h1[N_MAX * 4];    // h1 = x@W1   [N,16] as float4[N*4]
__device__ float4 g_agg1[N_MAX * 4];  // layer-1 aggregation target
__device__ float4 g_g2[N_MAX];        // relu(agg1+b1)@W2  [N,4]

__device__ __forceinline__ void red_v4(float* p, float4 v) {
    asm volatile("red.global.add.v4.f32 [%0], {%1, %2, %3, %4};"
                 :: "l"(p), "f"(v.x), "f"(v.y), "f"(v.z), "f"(v.w)
                 : "memory");
}

// ---------------------------------------------------------------- degree init
__global__ void k_init_deg(int n) {
    int i = blockIdx.x * blockDim.x + threadIdx.x;
    if (i < n) g_deg[i] = 1;  // self loop
}

// ------------------------------------------- edge split + degree count
__global__ void k_edges(const int* __restrict__ ei, int E) {
    int e = blockIdx.x * blockDim.x + threadIdx.x;
    if (e < E) {
        int s = ei[e];
        int d = ei[E + e];
        g_src[e] = s;
        g_dst[e] = d;
        atomicAdd(&g_deg[d], 1);
    }
}

// ---------------------------------------------------------------------- dinv
__global__ void k_dinv(int n) {
    int i = blockIdx.x * blockDim.x + threadIdx.x;
    if (i < n) g_dinv[i] = rsqrtf((float)g_deg[i]);
}

// ------------------------------------- GEMM1: h1 = x@W1 ; agg1 = h1 * dinv^2
// 128 threads/block, each thread -> one (node, f) output.  W1 in shared.
__global__ void k_gemm1(const float* __restrict__ x,
                        const float* __restrict__ W1, int n) {
    __shared__ float Ws[128 * F1];  // 8KB
    int tid = threadIdx.x;
    for (int i = tid; i < 128 * F1; i += 128) Ws[i] = W1[i];
    __syncthreads();

    int idx = blockIdx.x * 128 + tid;
    if (idx >= n * F1) return;
    int node = idx >> 4;
    int f    = idx & 15;

    const float4* x4 = (const float4*)(x + (size_t)node * 128);
    float acc = 0.f;
#pragma unroll
    for (int k = 0; k < 32; k++) {
        float4 xv = x4[k];
        acc += xv.x * Ws[(4 * k + 0) * F1 + f];
        acc += xv.y * Ws[(4 * k + 1) * F1 + f];
        acc += xv.z * Ws[(4 * k + 2) * F1 + f];
        acc += xv.w * Ws[(4 * k + 3) * F1 + f];
    }
    ((float*)g_h1)[idx] = acc;
    float di = g_dinv[node];
    ((float*)g_agg1)[idx] = acc * di * di;  // self-loop contribution
}

// ------------------------------ scatter layer 1: 4 threads per edge (float4 each)
__global__ void k_scatter1(int E) {
    int idx = blockIdx.x * blockDim.x + threadIdx.x;
    if (idx >= 4 * E) return;
    int e = idx >> 2;
    int c = idx & 3;
    int s = g_src[e];
    int d = g_dst[e];
    float nrm = g_dinv[s] * g_dinv[d];
    if (c == 0) g_norm[e] = nrm;  // reused by layer 2
    float4 v = g_h1[s * 4 + c];
    v.x *= nrm; v.y *= nrm; v.z *= nrm; v.w *= nrm;
    red_v4((float*)&g_agg1[d * 4 + c], v);
}

// ---------- fused: h2 = relu(agg1+b1); g2 = h2@W2; out init = g2*dinv^2
__global__ void k_layer2(const float* __restrict__ b1,
                         const float* __restrict__ W2,
                         int n, float4* __restrict__ out) {
    __shared__ float W2s[F1 * F2];  // 64
    __shared__ float b1s[F1];
    int tid = threadIdx.x;
    if (tid < F1 * F2) W2s[tid] = W2[tid];
    if (tid < F1)      b1s[tid] = b1[tid];
    __syncthreads();

    int i = blockIdx.x * blockDim.x + tid;
    if (i >= n) return;

    float h[F1];
#pragma unroll
    for (int q = 0; q < 4; q++) {
        float4 a = g_agg1[i * 4 + q];
        h[4 * q + 0] = fmaxf(a.x + b1s[4 * q + 0], 0.f);
        h[4 * q + 1] = fmaxf(a.y + b1s[4 * q + 1], 0.f);
        h[4 * q + 2] = fmaxf(a.z + b1s[4 * q + 2], 0.f);
        h[4 * q + 3] = fmaxf(a.w + b1s[4 * q + 3], 0.f);
    }
    float o0 = 0.f, o1 = 0.f, o2 = 0.f, o3 = 0.f;
#pragma unroll
    for (int k = 0; k < F1; k++) {
        float hk = h[k];
        o0 += hk * W2s[k * 4 + 0];
        o1 += hk * W2s[k * 4 + 1];
        o2 += hk * W2s[k * 4 + 2];
        o3 += hk * W2s[k * 4 + 3];
    }
    float4 g = make_float4(o0, o1, o2, o3);
    g_g2[i] = g;
    float di = g_dinv[i];
    float sl = di * di;
    out[i] = make_float4(o0 * sl, o1 * sl, o2 * sl, o3 * sl);
}

// ------------------------------ scatter layer 2: 1 thread per edge, v4 red
__global__ void k_scatter2(int E, float4* __restrict__ out) {
    int e = blockIdx.x * blockDim.x + threadIdx.x;
    if (e >= E) return;
    int s = g_src[e];
    int d = g_dst[e];
    float nrm = g_norm[e];
    float4 v = g_g2[s];
    v.x *= nrm; v.y *= nrm; v.z *= nrm; v.w *= nrm;
    red_v4((float*)&out[d], v);
}

// ---------------------------------------- bias + log_softmax over 4 classes
__global__ void k_final(const float* __restrict__ b2, int n,
                        float4* __restrict__ out) {
    int i = blockIdx.x * blockDim.x + threadIdx.x;
    if (i >= n) return;
    float4 v = out[i];
    float c0 = v.x + b2[0];
    float c1 = v.y + b2[1];
    float c2 = v.z + b2[2];
    float c3 = v.w + b2[3];
    float m = fmaxf(fmaxf(c0, c1), fmaxf(c2, c3));
    float e0 = __expf(c0 - m), e1 = __expf(c1 - m),
          e2 = __expf(c2 - m), e3 = __expf(c3 - m);
    float lse = m + logf(e0 + e1 + e2 + e3);
    out[i] = make_float4(c0 - lse, c1 - lse, c2 - lse, c3 - lse);
}

extern "C" void kernel_launch(void* const* d_in, const int* in_sizes, int n_in,
                              void* d_out, int out_size) {
    const float* x  = (const float*)d_in[0];
    const int*   ei = (const int*)d_in[1];
    const float* W1 = (const float*)d_in[2];
    const float* b1 = (const float*)d_in[3];
    const float* W2 = (const float*)d_in[4];
    const float* b2 = (const float*)d_in[5];
    float4* out = (float4*)d_out;

    int N = in_sizes[0] / 128;   // 100000
    int E = in_sizes[1] / 2;     // 3200000

    const int T = 256;

    k_init_deg<<<(N + T - 1) / T, T>>>(N);
    k_edges<<<(E + T - 1) / T, T>>>(ei, E);
    k_dinv<<<(N + T - 1) / T, T>>>(N);
    k_gemm1<<<(N * F1 + 127) / 128, 128>>>(x, W1, N);
    k_scatter1<<<(4 * E + T - 1) / T, T>>>(E);
    k_layer2<<<(N + 127) / 128, 128>>>(b1, W2, N, out);
    k_scatter2<<<(E + T - 1) / T, T>>>(E, out);
    k_final<<<(N + T - 1) / T, T>>>(b2, N, out);
}

// round 3
// speedup vs baseline: 1.0886x; 1.0886x over previous
#include <cuda_runtime.h>
#include <cuda_bf16.h>

// GCN 2-layer: x[100000,128] @ W1[128,16] -> aggregate -> relu -> @ W2[16,4]
// -> aggregate -> log_softmax.  Edges: int32 [2, 3200000].

#define N_MAX 100000
#define E_MAX 3200000
#define F1 16
#define F2 4

// Scratch (static __device__ — no allocation allowed)
__device__ float  g_dinv[N_MAX];
__device__ int    g_deg[N_MAX];
__device__ float4 g_h1[N_MAX * 4];    // h1 = x@W1   [N,16] as float4[N*4]
__device__ float4 g_agg1[N_MAX * 4];  // layer-1 aggregation target
__device__ float4 g_g2[N_MAX];        // relu(agg1+b1)@W2  [N,4]

__device__ __forceinline__ void red_v4(float* p, float4 v) {
    asm volatile("red.global.add.v4.f32 [%0], {%1, %2, %3, %4};"
                 :: "l"(p), "f"(v.x), "f"(v.y), "f"(v.z), "f"(v.w)
                 : "memory");
}

// ---------------------------------------------------------------- degree init
__global__ void k_init_deg(int n) {
    int i = blockIdx.x * blockDim.x + threadIdx.x;
    if (i < n) g_deg[i] = 1;  // self loop
}

// ---------------------------------------------------------- degree count only
__global__ void k_edges(const int* __restrict__ ei, int E) {
    int e = blockIdx.x * blockDim.x + threadIdx.x;
    if (e < E) atomicAdd(&g_deg[ei[E + e]], 1);
}

// ---------------------------------------------------------------------- dinv
__global__ void k_dinv(int n) {
    int i = blockIdx.x * blockDim.x + threadIdx.x;
    if (i < n) g_dinv[i] = rsqrtf((float)g_deg[i]);
}

// ------------------------------------- GEMM1: h1 = x@W1 ; agg1 = h1 * dinv^2
// Block: 128 threads, 64 nodes. x tile staged in smem (padded, conflict-free),
// 2 threads per node, 8 output features each, W broadcast from smem.
#define G1_NODES 64
#define G1_PAD 129
__global__ void __launch_bounds__(128) k_gemm1(const float* __restrict__ x,
                                               const float* __restrict__ W1,
                                               int n) {
    __shared__ float xs[G1_NODES * G1_PAD];  // ~33KB
    __shared__ float Ws[128 * F1];           // 8KB
    int tid = threadIdx.x;
    int base = blockIdx.x * G1_NODES;
    int nodes = min(G1_NODES, n - base);

    for (int i = tid; i < 128 * F1; i += 128) Ws[i] = W1[i];

    // Coalesced load of x tile: nodes*32 float4s
    const float4* xg = (const float4*)(x + (size_t)base * 128);
    for (int j = tid; j < nodes * 32; j += 128) {
        int row = j >> 5, c = (j & 31) << 2;
        float4 v = xg[j];
        float* dst = &xs[row * G1_PAD + c];
        dst[0] = v.x; dst[1] = v.y; dst[2] = v.z; dst[3] = v.w;
    }
    __syncthreads();

    int node_l = tid >> 1;          // 0..63
    int half   = tid & 1;           // 0/1 -> features 8*half..8*half+7
    if (node_l >= nodes) return;

    float acc[8];
#pragma unroll
    for (int j = 0; j < 8; j++) acc[j] = 0.f;

    const float* xrow = &xs[node_l * G1_PAD];
#pragma unroll 8
    for (int k = 0; k < 128; k++) {
        float xv = xrow[k];
        const float4* wr = (const float4*)&Ws[k * F1 + 8 * half];
        float4 w0 = wr[0], w1 = wr[1];
        acc[0] += xv * w0.x; acc[1] += xv * w0.y;
        acc[2] += xv * w0.z; acc[3] += xv * w0.w;
        acc[4] += xv * w1.x; acc[5] += xv * w1.y;
        acc[6] += xv * w1.z; acc[7] += xv * w1.w;
    }

    int node = base + node_l;
    float di = g_dinv[node];
    float sl = di * di;
    float4 a0 = make_float4(acc[0], acc[1], acc[2], acc[3]);
    float4 a1 = make_float4(acc[4], acc[5], acc[6], acc[7]);
    g_h1[node * 4 + 2 * half]     = a0;
    g_h1[node * 4 + 2 * half + 1] = a1;
    g_agg1[node * 4 + 2 * half]     = make_float4(a0.x*sl, a0.y*sl, a0.z*sl, a0.w*sl);
    g_agg1[node * 4 + 2 * half + 1] = make_float4(a1.x*sl, a1.y*sl, a1.z*sl, a1.w*sl);
}

// ------------------------------ scatter layer 1: 4 threads per edge (float4 each)
__global__ void k_scatter1(const int* __restrict__ ei, int E) {
    int idx = blockIdx.x * blockDim.x + threadIdx.x;
    if (idx >= 4 * E) return;
    int e = idx >> 2;
    int c = idx & 3;
    int s = ei[e];
    int d = ei[E + e];
    float nrm = g_dinv[s] * g_dinv[d];
    float4 v = g_h1[s * 4 + c];
    v.x *= nrm; v.y *= nrm; v.z *= nrm; v.w *= nrm;
    red_v4((float*)&g_agg1[d * 4 + c], v);
}

// ---------- fused: h2 = relu(agg1+b1); g2 = h2@W2; out init = g2*dinv^2
__global__ void k_layer2(const float* __restrict__ b1,
                         const float* __restrict__ W2,
                         int n, float4* __restrict__ out) {
    __shared__ float W2s[F1 * F2];
    __shared__ float b1s[F1];
    int tid = threadIdx.x;
    if (tid < F1 * F2) W2s[tid] = W2[tid];
    if (tid < F1)      b1s[tid] = b1[tid];
    __syncthreads();

    int i = blockIdx.x * blockDim.x + tid;
    if (i >= n) return;

    float h[F1];
#pragma unroll
    for (int q = 0; q < 4; q++) {
        float4 a = g_agg1[i * 4 + q];
        h[4 * q + 0] = fmaxf(a.x + b1s[4 * q + 0], 0.f);
        h[4 * q + 1] = fmaxf(a.y + b1s[4 * q + 1], 0.f);
        h[4 * q + 2] = fmaxf(a.z + b1s[4 * q + 2], 0.f);
        h[4 * q + 3] = fmaxf(a.w + b1s[4 * q + 3], 0.f);
    }
    float o0 = 0.f, o1 = 0.f, o2 = 0.f, o3 = 0.f;
#pragma unroll
    for (int k = 0; k < F1; k++) {
        float hk = h[k];
        o0 += hk * W2s[k * 4 + 0];
        o1 += hk * W2s[k * 4 + 1];
        o2 += hk * W2s[k * 4 + 2];
        o3 += hk * W2s[k * 4 + 3];
    }
    g_g2[i] = make_float4(o0, o1, o2, o3);
    float di = g_dinv[i];
    float sl = di * di;
    out[i] = make_float4(o0 * sl, o1 * sl, o2 * sl, o3 * sl);
}

// ------------------------------ scatter layer 2: 1 thread per edge, v4 red
__global__ void k_scatter2(const int* __restrict__ ei, int E,
                           float4* __restrict__ out) {
    int e = blockIdx.x * blockDim.x + threadIdx.x;
    if (e >= E) return;
    int s = ei[e];
    int d = ei[E + e];
    float nrm = g_dinv[s] * g_dinv[d];
    float4 v = g_g2[s];
    v.x *= nrm; v.y *= nrm; v.z *= nrm; v.w *= nrm;
    red_v4((float*)&out[d], v);
}

// ---------------------------------------- bias + log_softmax over 4 classes
__global__ void k_final(const float* __restrict__ b2, int n,
                        float4* __restrict__ out) {
    int i = blockIdx.x * blockDim.x + threadIdx.x;
    if (i >= n) return;
    float4 v = out[i];
    float c0 = v.x + b2[0];
    float c1 = v.y + b2[1];
    float c2 = v.z + b2[2];
    float c3 = v.w + b2[3];
    float m = fmaxf(fmaxf(c0, c1), fmaxf(c2, c3));
    float e0 = __expf(c0 - m), e1 = __expf(c1 - m),
          e2 = __expf(c2 - m), e3 = __expf(c3 - m);
    float lse = m + logf(e0 + e1 + e2 + e3);
    out[i] = make_float4(c0 - lse, c1 - lse, c2 - lse, c3 - lse);
}

extern "C" void kernel_launch(void* const* d_in, const int* in_sizes, int n_in,
                              void* d_out, int out_size) {
    const float* x  = (const float*)d_in[0];
    const int*   ei = (const int*)d_in[1];
    const float* W1 = (const float*)d_in[2];
    const float* b1 = (const float*)d_in[3];
    const float* W2 = (const float*)d_in[4];
    const float* b2 = (const float*)d_in[5];
    float4* out = (float4*)d_out;

    int N = in_sizes[0] / 128;   // 100000
    int E = in_sizes[1] / 2;     // 3200000

    const int T = 256;

    k_init_deg<<<(N + T - 1) / T, T>>>(N);
    k_edges<<<(E + T - 1) / T, T>>>(ei, E);
    k_dinv<<<(N + T - 1) / T, T>>>(N);
    k_gemm1<<<(N + G1_NODES - 1) / G1_NODES, 128>>>(x, W1, N);
    k_scatter1<<<(4 * E + T - 1) / T, T>>>(ei, E);
    k_layer2<<<(N + 127) / 128, 128>>>(b1, W2, N, out);
    k_scatter2<<<(E + T - 1) / T, T>>>(ei, E, out);
    k_final<<<(N + T - 1) / T, T>>>(b2, N, out);
}

// round 4
// speedup vs baseline: 1.1852x; 1.0887x over previous
#include <cuda_runtime.h>
#include <cuda_bf16.h>

// GCN 2-layer: x[100000,128] @ W1[128,16] -> aggregate -> relu -> @ W2[16,4]
// -> aggregate -> log_softmax.  Edges: int32 [2, 3200000].

#define N_MAX 100000
#define E_MAX 3200000
#define F1 16
#define F2 4

// Scratch (static __device__ — no allocation allowed)
__device__ float  g_dinv[N_MAX];
__device__ int    g_deg[N_MAX];
__device__ float4 g_hs[N_MAX * 4];    // hs = (x@W1) * dinv   [N,16]
__device__ float4 g_agg1[N_MAX * 4];  // layer-1 aggregation target
__device__ float4 g_g2s[N_MAX];       // (relu(agg1+b1)@W2) * dinv  [N,4]

__device__ __forceinline__ void red_v4(float* p, float4 v) {
    asm volatile("red.global.add.v4.f32 [%0], {%1, %2, %3, %4};"
                 :: "l"(p), "f"(v.x), "f"(v.y), "f"(v.z), "f"(v.w)
                 : "memory");
}

// ---------------------------------------------------------------- degree init
__global__ void k_init_deg(int n) {
    int i = blockIdx.x * blockDim.x + threadIdx.x;
    if (i < n) g_deg[i] = 1;  // self loop
}

// ---------------------------------------------------------- degree count only
__global__ void k_edges(const int* __restrict__ ei, int E) {
    int e = blockIdx.x * blockDim.x + threadIdx.x;
    if (e < E) atomicAdd(&g_deg[ei[E + e]], 1);
}

// ---------------------------------------------------------------------- dinv
__global__ void k_dinv(int n) {
    int i = blockIdx.x * blockDim.x + threadIdx.x;
    if (i < n) g_dinv[i] = rsqrtf((float)g_deg[i]);
}

// --------------------- GEMM1: hs = (x@W1)*dinv ; agg1 = hs*dinv (self loop)
// 256 threads, 64 nodes/block, 4 threads per node (one feature-quad each).
// x staged in smem with 132-float row stride (16B aligned, conflict-free).
#define G1_NODES 64
#define G1_PADF4 33   // row stride in float4 (132 floats)
__global__ void __launch_bounds__(256) k_gemm1(const float* __restrict__ x,
                                               const float* __restrict__ W1,
                                               int n) {
    __shared__ float4 xs[G1_NODES * G1_PADF4];  // 33.8KB
    __shared__ float4 Ws[128 * 4];              // 8KB: W row k -> 4 float4
    int tid = threadIdx.x;
    int base = blockIdx.x * G1_NODES;
    int nodes = min(G1_NODES, n - base);

    for (int i = tid; i < 128 * 4; i += 256) Ws[i] = ((const float4*)W1)[i];

    const float4* xg = (const float4*)(x + (size_t)base * 128);
    for (int j = tid; j < nodes * 32; j += 256) {
        int row = j >> 5, c = j & 31;
        xs[row * G1_PADF4 + c] = xg[j];
    }
    __syncthreads();

    int node_l = tid >> 2;   // 0..63
    int q      = tid & 3;    // feature quad
    if (node_l >= nodes) return;

    float4 acc = make_float4(0.f, 0.f, 0.f, 0.f);
    const float4* xr = &xs[node_l * G1_PADF4];
#pragma unroll 8
    for (int kc = 0; kc < 32; kc++) {
        float4 xv = xr[kc];
        const float4* w = &Ws[kc * 16 + q];
        float4 w0 = w[0], w1 = w[4], w2 = w[8], w3 = w[12];
        acc.x += xv.x * w0.x + xv.y * w1.x + xv.z * w2.x + xv.w * w3.x;
        acc.y += xv.x * w0.y + xv.y * w1.y + xv.z * w2.y + xv.w * w3.y;
        acc.z += xv.x * w0.z + xv.y * w1.z + xv.z * w2.z + xv.w * w3.z;
        acc.w += xv.x * w0.w + xv.y * w1.w + xv.z * w2.w + xv.w * w3.w;
    }

    int node = base + node_l;
    float di = g_dinv[node];
    float4 hs = make_float4(acc.x * di, acc.y * di, acc.z * di, acc.w * di);
    g_hs[node * 4 + q] = hs;
    g_agg1[node * 4 + q] = make_float4(hs.x * di, hs.y * di, hs.z * di, hs.w * di);
}

// -------------------- scatter layer 1: 4 threads per edge (float4 each)
// msg = hs[s] * dinv[d]   (src norm pre-folded into hs)
__global__ void k_scatter1(const int* __restrict__ ei, int E) {
    int idx = blockIdx.x * blockDim.x + threadIdx.x;
    if (idx >= 4 * E) return;
    int e = idx >> 2;
    int c = idx & 3;
    int s = ei[e];
    int d = ei[E + e];
    float nrm = g_dinv[d];
    float4 v = g_hs[s * 4 + c];
    v.x *= nrm; v.y *= nrm; v.z *= nrm; v.w *= nrm;
    red_v4((float*)&g_agg1[d * 4 + c], v);
}

// ---------- fused: h2 = relu(agg1+b1); g2s = (h2@W2)*dinv; out init = g2s*dinv
__global__ void k_layer2(const float* __restrict__ b1,
                         const float* __restrict__ W2,
                         int n, float4* __restrict__ out) {
    __shared__ float W2s[F1 * F2];
    __shared__ float b1s[F1];
    int tid = threadIdx.x;
    if (tid < F1 * F2) W2s[tid] = W2[tid];
    if (tid < F1)      b1s[tid] = b1[tid];
    __syncthreads();

    int i = blockIdx.x * blockDim.x + tid;
    if (i >= n) return;

    float h[F1];
#pragma unroll
    for (int q = 0; q < 4; q++) {
        float4 a = g_agg1[i * 4 + q];
        h[4 * q + 0] = fmaxf(a.x + b1s[4 * q + 0], 0.f);
        h[4 * q + 1] = fmaxf(a.y + b1s[4 * q + 1], 0.f);
        h[4 * q + 2] = fmaxf(a.z + b1s[4 * q + 2], 0.f);
        h[4 * q + 3] = fmaxf(a.w + b1s[4 * q + 3], 0.f);
    }
    float o0 = 0.f, o1 = 0.f, o2 = 0.f, o3 = 0.f;
#pragma unroll
    for (int k = 0; k < F1; k++) {
        float hk = h[k];
        o0 += hk * W2s[k * 4 + 0];
        o1 += hk * W2s[k * 4 + 1];
        o2 += hk * W2s[k * 4 + 2];
        o3 += hk * W2s[k * 4 + 3];
    }
    float di = g_dinv[i];
    float4 g2s = make_float4(o0 * di, o1 * di, o2 * di, o3 * di);
    g_g2s[i] = g2s;
    out[i] = make_float4(g2s.x * di, g2s.y * di, g2s.z * di, g2s.w * di);
}

// ------------------------------ scatter layer 2: 1 thread per edge, v4 red
__global__ void k_scatter2(const int* __restrict__ ei, int E,
                           float4* __restrict__ out) {
    int e = blockIdx.x * blockDim.x + threadIdx.x;
    if (e >= E) return;
    int s = ei[e];
    int d = ei[E + e];
    float nrm = g_dinv[d];
    float4 v = g_g2s[s];
    v.x *= nrm; v.y *= nrm; v.z *= nrm; v.w *= nrm;
    red_v4((float*)&out[d], v);
}

// ---------------------------------------- bias + log_softmax over 4 classes
__global__ void k_final(const float* __restrict__ b2, int n,
                        float4* __restrict__ out) {
    int i = blockIdx.x * blockDim.x + threadIdx.x;
    if (i >= n) return;
    float4 v = out[i];
    float c0 = v.x + b2[0];
    float c1 = v.y + b2[1];
    float c2 = v.z + b2[2];
    float c3 = v.w + b2[3];
    float m = fmaxf(fmaxf(c0, c1), fmaxf(c2, c3));
    float e0 = __expf(c0 - m), e1 = __expf(c1 - m),
          e2 = __expf(c2 - m), e3 = __expf(c3 - m);
    float lse = m + logf(e0 + e1 + e2 + e3);
    out[i] = make_float4(c0 - lse, c1 - lse, c2 - lse, c3 - lse);
}

extern "C" void kernel_launch(void* const* d_in, const int* in_sizes, int n_in,
                              void* d_out, int out_size) {
    const float* x  = (const float*)d_in[0];
    const int*   ei = (const int*)d_in[1];
    const float* W1 = (const float*)d_in[2];
    const float* b1 = (const float*)d_in[3];
    const float* W2 = (const float*)d_in[4];
    const float* b2 = (const float*)d_in[5];
    float4* out = (float4*)d_out;

    int N = in_sizes[0] / 128;   // 100000
    int E = in_sizes[1] / 2;     // 3200000

    const int T = 256;

    k_init_deg<<<(N + T - 1) / T, T>>>(N);
    k_edges<<<(E + T - 1) / T, T>>>(ei, E);
    k_dinv<<<(N + T - 1) / T, T>>>(N);
    k_gemm1<<<(N + G1_NODES - 1) / G1_NODES, 256>>>(x, W1, N);
    k_scatter1<<<(4 * E + T - 1) / T, T>>>(ei, E);
    k_layer2<<<(N + 127) / 128, 128>>>(b1, W2, N, out);
    k_scatter2<<<(E + T - 1) / T, T>>>(ei, E, out);
    k_final<<<(N + T - 1) / T, T>>>(b2, N, out);
}

// round 5
// speedup vs baseline: 1.2152x; 1.0253x over previous
#include <cuda_runtime.h>
#include <cuda_bf16.h>

// GCN 2-layer, CSR pull-mode (no float atomics).
// x[100000,128] @ W1[128,16] -> aggregate -> relu -> @ W2[16,4]
// -> aggregate -> log_softmax.  Edges: int32 [2, 3200000].

#define N_MAX 100000
#define E_MAX 3200000
#define F1 16
#define F2 4
#define SCAN_T 256
#define NBLK ((N_MAX + SCAN_T - 1) / SCAN_T)   // 391

// Scratch (static __device__ — no allocation allowed)
__device__ int    g_deg[N_MAX];      // in-degree + 1 (self loop)
__device__ float  g_dinv[N_MAX];
__device__ int    g_offs[N_MAX];     // CSR offsets (exclusive scan of deg-1)
__device__ int    g_cursor[N_MAX];
__device__ int    g_bsum[NBLK];
__device__ int    g_csr[E_MAX];      // src node per incoming edge, grouped by dst
__device__ float4 g_hs[N_MAX * 4];   // hs = (x@W1) * dinv   [N,16]
__device__ float4 g_g2s[N_MAX];      // (relu(agg1+b1)@W2) * dinv  [N,4]

// ---------------------------------------------------------------- degree init
__global__ void k_init_deg(int n) {
    int i = blockIdx.x * blockDim.x + threadIdx.x;
    if (i < n) g_deg[i] = 1;  // self loop
}

// ---------------------------------------------------------- degree count
__global__ void k_count(const int* __restrict__ ei, int E) {
    int e = blockIdx.x * blockDim.x + threadIdx.x;
    if (e < E) atomicAdd(&g_deg[ei[E + e]], 1);
}

// ---------------------------------------------------------------------- dinv
__global__ void k_dinv(int n) {
    int i = blockIdx.x * blockDim.x + threadIdx.x;
    if (i < n) g_dinv[i] = rsqrtf((float)g_deg[i]);
}

// ------------------------------------------------- scan stage 1: per-block
__global__ void k_scan_block(int n) {
    __shared__ int sh[SCAN_T];
    int i = blockIdx.x * SCAN_T + threadIdx.x;
    int v = (i < n) ? (g_deg[i] - 1) : 0;
    sh[threadIdx.x] = v;
    __syncthreads();
#pragma unroll
    for (int ofs = 1; ofs < SCAN_T; ofs <<= 1) {
        int t = (threadIdx.x >= ofs) ? sh[threadIdx.x - ofs] : 0;
        __syncthreads();
        sh[threadIdx.x] += t;
        __syncthreads();
    }
    if (i < n) g_offs[i] = sh[threadIdx.x] - v;  // exclusive
    if (threadIdx.x == SCAN_T - 1) g_bsum[blockIdx.x] = sh[threadIdx.x];
}

// ------------------------------------------------- scan stage 2: block sums
__global__ void k_scan_mid(int nb) {
    __shared__ int sh[512];
    int t = threadIdx.x;
    int v = (t < nb) ? g_bsum[t] : 0;
    sh[t] = v;
    __syncthreads();
#pragma unroll
    for (int ofs = 1; ofs < 512; ofs <<= 1) {
        int u = (t >= ofs) ? sh[t - ofs] : 0;
        __syncthreads();
        sh[t] += u;
        __syncthreads();
    }
    if (t < nb) g_bsum[t] = sh[t] - v;  // exclusive
}

// ------------------------------------------------- scan stage 3: add + cursor
__global__ void k_scan_add(int n) {
    int i = blockIdx.x * SCAN_T + threadIdx.x;
    if (i < n) {
        int o = g_offs[i] + g_bsum[blockIdx.x];
        g_offs[i] = o;
        g_cursor[i] = o;
    }
}

// ------------------------------------------------- CSR fill (int atomics only)
__global__ void k_fill(const int* __restrict__ ei, int E) {
    int e = blockIdx.x * blockDim.x + threadIdx.x;
    if (e < E) {
        int s = ei[e];
        int d = ei[E + e];
        int p = atomicAdd(&g_cursor[d], 1);
        g_csr[p] = s;
    }
}

// --------------------- GEMM1: hs = (x@W1)*dinv
// 256 threads, 64 nodes/block, 4 threads per node (one feature-quad each).
#define G1_NODES 64
#define G1_PADF4 33
__global__ void __launch_bounds__(256) k_gemm1(const float* __restrict__ x,
                                               const float* __restrict__ W1,
                                               int n) {
    __shared__ float4 xs[G1_NODES * G1_PADF4];
    __shared__ float4 Ws[128 * 4];
    int tid = threadIdx.x;
    int base = blockIdx.x * G1_NODES;
    int nodes = min(G1_NODES, n - base);

    for (int i = tid; i < 128 * 4; i += 256) Ws[i] = ((const float4*)W1)[i];

    const float4* xg = (const float4*)(x + (size_t)base * 128);
    for (int j = tid; j < nodes * 32; j += 256) {
        int row = j >> 5, c = j & 31;
        xs[row * G1_PADF4 + c] = xg[j];
    }
    __syncthreads();

    int node_l = tid >> 2;
    int q      = tid & 3;
    if (node_l >= nodes) return;

    float4 acc = make_float4(0.f, 0.f, 0.f, 0.f);
    const float4* xr = &xs[node_l * G1_PADF4];
#pragma unroll 8
    for (int kc = 0; kc < 32; kc++) {
        float4 xv = xr[kc];
        const float4* w = &Ws[kc * 16 + q];
        float4 w0 = w[0], w1 = w[4], w2 = w[8], w3 = w[12];
        acc.x += xv.x * w0.x + xv.y * w1.x + xv.z * w2.x + xv.w * w3.x;
        acc.y += xv.x * w0.y + xv.y * w1.y + xv.z * w2.y + xv.w * w3.y;
        acc.z += xv.x * w0.z + xv.y * w1.z + xv.z * w2.z + xv.w * w3.z;
        acc.w += xv.x * w0.w + xv.y * w1.w + xv.z * w2.w + xv.w * w3.w;
    }

    int node = base + node_l;
    float di = g_dinv[node];
    g_hs[node * 4 + q] = make_float4(acc.x * di, acc.y * di, acc.z * di, acc.w * di);
}

// ---------- fused pull-agg1 + bias/relu + GEMM2: g2s = (relu(agg+b1)@W2)*dinv
// 4 lanes per node (quad handles feature quad q). Quad shuffle-reduce for GEMM2.
__global__ void __launch_bounds__(256) k_agg1_l2(const float* __restrict__ b1,
                                                 const float* __restrict__ W2,
                                                 int n) {
    __shared__ float4 W2s[F1];   // W2 row k -> float4 of 4 classes
    __shared__ float4 b1s[4];
    int tid = threadIdx.x;
    if (tid < F1) W2s[tid] = make_float4(W2[tid*4], W2[tid*4+1], W2[tid*4+2], W2[tid*4+3]);
    if (tid < 4)  b1s[tid] = ((const float4*)b1)[tid];
    __syncthreads();

    int idx = blockIdx.x * 256 + tid;
    int node = idx >> 2;
    int q    = idx & 3;
    bool valid = node < n;
    if (node >= n) node = n - 1;   // clamp; quads stay lockstep for shuffles

    int off = g_offs[node];
    int cnt = g_deg[node] - 1;

    float4 acc = make_float4(0.f, 0.f, 0.f, 0.f);
    int j = 0;
    for (; j + 4 <= cnt; j += 4) {
        int s0 = g_csr[off + j + 0];
        int s1 = g_csr[off + j + 1];
        int s2 = g_csr[off + j + 2];
        int s3 = g_csr[off + j + 3];
        float4 v0 = g_hs[s0 * 4 + q];
        float4 v1 = g_hs[s1 * 4 + q];
        float4 v2 = g_hs[s2 * 4 + q];
        float4 v3 = g_hs[s3 * 4 + q];
        acc.x += v0.x + v1.x + v2.x + v3.x;
        acc.y += v0.y + v1.y + v2.y + v3.y;
        acc.z += v0.z + v1.z + v2.z + v3.z;
        acc.w += v0.w + v1.w + v2.w + v3.w;
    }
    for (; j < cnt; j++) {
        int s = g_csr[off + j];
        float4 v = g_hs[s * 4 + q];
        acc.x += v.x; acc.y += v.y; acc.z += v.z; acc.w += v.w;
    }

    float di = g_dinv[node];
    float4 hq = g_hs[node * 4 + q];   // self loop (src norm already folded)
    float4 b = b1s[q];
    float h0 = fmaxf(di * (acc.x + hq.x) + b.x, 0.f);
    float h1 = fmaxf(di * (acc.y + hq.y) + b.y, 0.f);
    float h2 = fmaxf(di * (acc.z + hq.z) + b.z, 0.f);
    float h3 = fmaxf(di * (acc.w + hq.w) + b.w, 0.f);

    float4 w0 = W2s[4 * q + 0], w1 = W2s[4 * q + 1],
           w2 = W2s[4 * q + 2], w3 = W2s[4 * q + 3];
    float4 o;
    o.x = h0 * w0.x + h1 * w1.x + h2 * w2.x + h3 * w3.x;
    o.y = h0 * w0.y + h1 * w1.y + h2 * w2.y + h3 * w3.y;
    o.z = h0 * w0.z + h1 * w1.z + h2 * w2.z + h3 * w3.z;
    o.w = h0 * w0.w + h1 * w1.w + h2 * w2.w + h3 * w3.w;

    // reduce across the 4-lane quad
    o.x += __shfl_xor_sync(0xffffffffu, o.x, 1);
    o.y += __shfl_xor_sync(0xffffffffu, o.y, 1);
    o.z += __shfl_xor_sync(0xffffffffu, o.z, 1);
    o.w += __shfl_xor_sync(0xffffffffu, o.w, 1);
    o.x += __shfl_xor_sync(0xffffffffu, o.x, 2);
    o.y += __shfl_xor_sync(0xffffffffu, o.y, 2);
    o.z += __shfl_xor_sync(0xffffffffu, o.z, 2);
    o.w += __shfl_xor_sync(0xffffffffu, o.w, 2);

    if (q == 0 && valid)
        g_g2s[node] = make_float4(o.x * di, o.y * di, o.z * di, o.w * di);
}

// ---------- fused pull-agg2 + bias + log_softmax -> out
__global__ void k_agg2_final(const float* __restrict__ b2, int n,
                             float4* __restrict__ out) {
    int i = blockIdx.x * blockDim.x + threadIdx.x;
    if (i >= n) return;

    int off = g_offs[i];
    int cnt = g_deg[i] - 1;

    float4 acc = make_float4(0.f, 0.f, 0.f, 0.f);
    int j = 0;
    for (; j + 4 <= cnt; j += 4) {
        int s0 = g_csr[off + j + 0];
        int s1 = g_csr[off + j + 1];
        int s2 = g_csr[off + j + 2];
        int s3 = g_csr[off + j + 3];
        float4 v0 = g_g2s[s0];
        float4 v1 = g_g2s[s1];
        float4 v2 = g_g2s[s2];
        float4 v3 = g_g2s[s3];
        acc.x += v0.x + v1.x + v2.x + v3.x;
        acc.y += v0.y + v1.y + v2.y + v3.y;
        acc.z += v0.z + v1.z + v2.z + v3.z;
        acc.w += v0.w + v1.w + v2.w + v3.w;
    }
    for (; j < cnt; j++) {
        float4 v = g_g2s[g_csr[off + j]];
        acc.x += v.x; acc.y += v.y; acc.z += v.z; acc.w += v.w;
    }

    float di = g_dinv[i];
    float4 gi = g_g2s[i];
    float c0 = di * (acc.x + gi.x) + b2[0];
    float c1 = di * (acc.y + gi.y) + b2[1];
    float c2 = di * (acc.z + gi.z) + b2[2];
    float c3 = di * (acc.w + gi.w) + b2[3];
    float m = fmaxf(fmaxf(c0, c1), fmaxf(c2, c3));
    float e0 = __expf(c0 - m), e1 = __expf(c1 - m),
          e2 = __expf(c2 - m), e3 = __expf(c3 - m);
    float lse = m + logf(e0 + e1 + e2 + e3);
    out[i] = make_float4(c0 - lse, c1 - lse, c2 - lse, c3 - lse);
}

extern "C" void kernel_launch(void* const* d_in, const int* in_sizes, int n_in,
                              void* d_out, int out_size) {
    const float* x  = (const float*)d_in[0];
    const int*   ei = (const int*)d_in[1];
    const float* W1 = (const float*)d_in[2];
    const float* b1 = (const float*)d_in[3];
    const float* W2 = (const float*)d_in[4];
    const float* b2 = (const float*)d_in[5];
    float4* out = (float4*)d_out;

    int N = in_sizes[0] / 128;   // 100000
    int E = in_sizes[1] / 2;     // 3200000
    int nblk = (N + SCAN_T - 1) / SCAN_T;

    const int T = 256;

    k_init_deg<<<(N + T - 1) / T, T>>>(N);
    k_count<<<(E + T - 1) / T, T>>>(ei, E);
    k_dinv<<<(N + T - 1) / T, T>>>(N);
    k_scan_block<<<nblk, SCAN_T>>>(N);
    k_scan_mid<<<1, 512>>>(nblk);
    k_scan_add<<<nblk, SCAN_T>>>(N);
    k_fill<<<(E + T - 1) / T, T>>>(ei, E);
    k_gemm1<<<(N + G1_NODES - 1) / G1_NODES, 256>>>(x, W1, N);
    k_agg1_l2<<<(4 * N + 255) / 256, 256>>>(b1, W2, N);
    k_agg2_final<<<(N + T - 1) / T, T>>>(b2, N, out);
}

// round 6
// speedup vs baseline: 1.2468x; 1.0260x over previous
#include <cuda_runtime.h>
#include <cuda_bf16.h>

// GCN 2-layer, CSR pull-mode (no float atomics).
// x[100000,128] @ W1[128,16] -> aggregate -> relu -> @ W2[16,4]
// -> aggregate -> log_softmax.  Edges: int32 [2, 3200000].

#define N_MAX 100000
#define E_MAX 3200000
#define F1 16
#define F2 4
#define SCAN_T 256
#define NBLK ((N_MAX + SCAN_T - 1) / SCAN_T)   // 391

__device__ int    g_deg[N_MAX];      // in-degree + 1 (self loop)
__device__ float  g_dinv[N_MAX];
__device__ int    g_offs[N_MAX];     // CSR offsets (exclusive scan of deg-1)
__device__ int    g_cursor[N_MAX];
__device__ int    g_bsum[NBLK];
__device__ int    g_csr[E_MAX];      // src per incoming edge, grouped by dst
__device__ float4 g_hs[N_MAX * 4];   // hs = (x@W1) * dinv   [N,16]
__device__ float4 g_g2s[N_MAX];      // (relu(agg1+b1)@W2) * dinv  [N,4]

// ---------------------------------------------------------------- degree init
__global__ void k_init_deg(int n) {
    int i = blockIdx.x * blockDim.x + threadIdx.x;
    if (i < n) g_deg[i] = 1;  // self loop
}

// ---------------------------------------------------------- degree count
__global__ void k_count(const int* __restrict__ ei, int E) {
    int e = blockIdx.x * blockDim.x + threadIdx.x;
    if (e < E) atomicAdd(&g_deg[ei[E + e]], 1);
}

// ------------------------------------------------- scan stage 1: per-block
__global__ void k_scan_block(int n) {
    __shared__ int sh[SCAN_T];
    int i = blockIdx.x * SCAN_T + threadIdx.x;
    int v = (i < n) ? (g_deg[i] - 1) : 0;
    sh[threadIdx.x] = v;
    __syncthreads();
#pragma unroll
    for (int ofs = 1; ofs < SCAN_T; ofs <<= 1) {
        int t = (threadIdx.x >= ofs) ? sh[threadIdx.x - ofs] : 0;
        __syncthreads();
        sh[threadIdx.x] += t;
        __syncthreads();
    }
    if (i < n) g_offs[i] = sh[threadIdx.x] - v;  // exclusive
    if (threadIdx.x == SCAN_T - 1) g_bsum[blockIdx.x] = sh[threadIdx.x];
}

// --------------------- GEMM1 (launch index 3 -> profiled): hs = (x@W1)*dinv
// 32 nodes/block, 128 threads, 4 threads per node. Small tiles => ~9 resident
// blocks/SM => DRAM loads stay in flight while other blocks compute.
#define G1_NODES 32
#define G1_PADF4 33
__global__ void __launch_bounds__(128) k_gemm1(const float* __restrict__ x,
                                               const float* __restrict__ W1,
                                               int n) {
    __shared__ float4 xs[G1_NODES * G1_PADF4];  // 16.9KB
    __shared__ float4 Ws[128 * 4];              // 8KB
    int tid = threadIdx.x;
    int base = blockIdx.x * G1_NODES;
    int nodes = min(G1_NODES, n - base);

    for (int i = tid; i < 128 * 4; i += 128) Ws[i] = ((const float4*)W1)[i];

    const float4* xg = (const float4*)(x + (size_t)base * 128);
    for (int j = tid; j < nodes * 32; j += 128) {
        int row = j >> 5, c = j & 31;
        xs[row * G1_PADF4 + c] = xg[j];
    }
    __syncthreads();

    int node_l = tid >> 2;
    int q      = tid & 3;
    if (node_l >= nodes) return;

    float4 acc = make_float4(0.f, 0.f, 0.f, 0.f);
    const float4* xr = &xs[node_l * G1_PADF4];
#pragma unroll 8
    for (int kc = 0; kc < 32; kc++) {
        float4 xv = xr[kc];
        const float4* w = &Ws[kc * 16 + q];
        float4 w0 = w[0], w1 = w[4], w2 = w[8], w3 = w[12];
        acc.x += xv.x * w0.x + xv.y * w1.x + xv.z * w2.x + xv.w * w3.x;
        acc.y += xv.x * w0.y + xv.y * w1.y + xv.z * w2.y + xv.w * w3.y;
        acc.z += xv.x * w0.z + xv.y * w1.z + xv.z * w2.z + xv.w * w3.z;
        acc.w += xv.x * w0.w + xv.y * w1.w + xv.z * w2.w + xv.w * w3.w;
    }

    int node = base + node_l;
    float di = rsqrtf((float)g_deg[node]);
    if (q == 0) g_dinv[node] = di;
    g_hs[node * 4 + q] = make_float4(acc.x * di, acc.y * di, acc.z * di, acc.w * di);
}

// ------------------------------------------------- scan stage 2: block sums
__global__ void k_scan_mid(int nb) {
    __shared__ int sh[512];
    int t = threadIdx.x;
    int v = (t < nb) ? g_bsum[t] : 0;
    sh[t] = v;
    __syncthreads();
#pragma unroll
    for (int ofs = 1; ofs < 512; ofs <<= 1) {
        int u = (t >= ofs) ? sh[t - ofs] : 0;
        __syncthreads();
        sh[t] += u;
        __syncthreads();
    }
    if (t < nb) g_bsum[t] = sh[t] - v;  // exclusive
}

// ------------------------------------------------- scan stage 3: add + cursor
__global__ void k_scan_add(int n) {
    int i = blockIdx.x * SCAN_T + threadIdx.x;
    if (i < n) {
        int o = g_offs[i] + g_bsum[blockIdx.x];
        g_offs[i] = o;
        g_cursor[i] = o;
    }
}

// ------------------------------------------------- CSR fill (int atomics only)
__global__ void k_fill(const int* __restrict__ ei, int E) {
    int e = blockIdx.x * blockDim.x + threadIdx.x;
    if (e < E) {
        int s = ei[e];
        int d = ei[E + e];
        int p = atomicAdd(&g_cursor[d], 1);
        g_csr[p] = s;
    }
}

// ---------- fused pull-agg1 + bias/relu + GEMM2: g2s = (relu(agg+b1)@W2)*dinv
__global__ void __launch_bounds__(256) k_agg1_l2(const float* __restrict__ b1,
                                                 const float* __restrict__ W2,
                                                 int n) {
    __shared__ float4 W2s[F1];
    __shared__ float4 b1s[4];
    int tid = threadIdx.x;
    if (tid < F1) W2s[tid] = make_float4(W2[tid*4], W2[tid*4+1], W2[tid*4+2], W2[tid*4+3]);
    if (tid < 4)  b1s[tid] = ((const float4*)b1)[tid];
    __syncthreads();

    int idx = blockIdx.x * 256 + tid;
    int node = idx >> 2;
    int q    = idx & 3;
    bool valid = node < n;
    if (node >= n) node = n - 1;   // clamp; quads stay lockstep for shuffles

    int off = g_offs[node];
    int cnt = g_deg[node] - 1;

    float4 acc = make_float4(0.f, 0.f, 0.f, 0.f);
    int j = 0;
    for (; j + 8 <= cnt; j += 8) {
        int sN[8];
#pragma unroll
        for (int u = 0; u < 8; u++) sN[u] = __ldg(&g_csr[off + j + u]);
        float4 vN[8];
#pragma unroll
        for (int u = 0; u < 8; u++) vN[u] = g_hs[sN[u] * 4 + q];
#pragma unroll
        for (int u = 0; u < 8; u++) {
            acc.x += vN[u].x; acc.y += vN[u].y;
            acc.z += vN[u].z; acc.w += vN[u].w;
        }
    }
    for (; j < cnt; j++) {
        float4 v = g_hs[__ldg(&g_csr[off + j]) * 4 + q];
        acc.x += v.x; acc.y += v.y; acc.z += v.z; acc.w += v.w;
    }

    float di = g_dinv[node];
    float4 hq = g_hs[node * 4 + q];   // self loop
    float4 b = b1s[q];
    float h0 = fmaxf(di * (acc.x + hq.x) + b.x, 0.f);
    float h1 = fmaxf(di * (acc.y + hq.y) + b.y, 0.f);
    float h2 = fmaxf(di * (acc.z + hq.z) + b.z, 0.f);
    float h3 = fmaxf(di * (acc.w + hq.w) + b.w, 0.f);

    float4 w0 = W2s[4 * q + 0], w1 = W2s[4 * q + 1],
           w2 = W2s[4 * q + 2], w3 = W2s[4 * q + 3];
    float4 o;
    o.x = h0 * w0.x + h1 * w1.x + h2 * w2.x + h3 * w3.x;
    o.y = h0 * w0.y + h1 * w1.y + h2 * w2.y + h3 * w3.y;
    o.z = h0 * w0.z + h1 * w1.z + h2 * w2.z + h3 * w3.z;
    o.w = h0 * w0.w + h1 * w1.w + h2 * w2.w + h3 * w3.w;

    o.x += __shfl_xor_sync(0xffffffffu, o.x, 1);
    o.y += __shfl_xor_sync(0xffffffffu, o.y, 1);
    o.z += __shfl_xor_sync(0xffffffffu, o.z, 1);
    o.w += __shfl_xor_sync(0xffffffffu, o.w, 1);
    o.x += __shfl_xor_sync(0xffffffffu, o.x, 2);
    o.y += __shfl_xor_sync(0xffffffffu, o.y, 2);
    o.z += __shfl_xor_sync(0xffffffffu, o.z, 2);
    o.w += __shfl_xor_sync(0xffffffffu, o.w, 2);

    if (q == 0 && valid)
        g_g2s[node] = make_float4(o.x * di, o.y * di, o.z * di, o.w * di);
}

// ---------- fused pull-agg2 + bias + log_softmax -> out
__global__ void k_agg2_final(const float* __restrict__ b2, int n,
                             float4* __restrict__ out) {
    int i = blockIdx.x * blockDim.x + threadIdx.x;
    if (i >= n) return;

    int off = g_offs[i];
    int cnt = g_deg[i] - 1;

    float4 acc = make_float4(0.f, 0.f, 0.f, 0.f);
    int j = 0;
    for (; j + 8 <= cnt; j += 8) {
        int sN[8];
#pragma unroll
        for (int u = 0; u < 8; u++) sN[u] = __ldg(&g_csr[off + j + u]);
        float4 vN[8];
#pragma unroll
        for (int u = 0; u < 8; u++) vN[u] = g_g2s[sN[u]];
#pragma unroll
        for (int u = 0; u < 8; u++) {
            acc.x += vN[u].x; acc.y += vN[u].y;
            acc.z += vN[u].z; acc.w += vN[u].w;
        }
    }
    for (; j < cnt; j++) {
        float4 v = g_g2s[__ldg(&g_csr[off + j])];
        acc.x += v.x; acc.y += v.y; acc.z += v.z; acc.w += v.w;
    }

    float di = g_dinv[i];
    float4 gi = g_g2s[i];
    float c0 = di * (acc.x + gi.x) + b2[0];
    float c1 = di * (acc.y + gi.y) + b2[1];
    float c2 = di * (acc.z + gi.z) + b2[2];
    float c3 = di * (acc.w + gi.w) + b2[3];
    float m = fmaxf(fmaxf(c0, c1), fmaxf(c2, c3));
    float e0 = __expf(c0 - m), e1 = __expf(c1 - m),
          e2 = __expf(c2 - m), e3 = __expf(c3 - m);
    float lse = m + logf(e0 + e1 + e2 + e3);
    out[i] = make_float4(c0 - lse, c1 - lse, c2 - lse, c3 - lse);
}

extern "C" void kernel_launch(void* const* d_in, const int* in_sizes, int n_in,
                              void* d_out, int out_size) {
    const float* x  = (const float*)d_in[0];
    const int*   ei = (const int*)d_in[1];
    const float* W1 = (const float*)d_in[2];
    const float* b1 = (const float*)d_in[3];
    const float* W2 = (const float*)d_in[4];
    const float* b2 = (const float*)d_in[5];
    float4* out = (float4*)d_out;

    int N = in_sizes[0] / 128;   // 100000
    int E = in_sizes[1] / 2;     // 3200000
    int nblk = (N + SCAN_T - 1) / SCAN_T;

    const int T = 256;

    k_init_deg<<<(N + T - 1) / T, T>>>(N);               // 0
    k_count<<<(E + T - 1) / T, T>>>(ei, E);              // 1
    k_scan_block<<<nblk, SCAN_T>>>(N);                   // 2
    k_gemm1<<<(N + G1_NODES - 1) / G1_NODES, 128>>>(x, W1, N);  // 3 (profiled)
    k_scan_mid<<<1, 512>>>(nblk);                        // 4
    k_scan_add<<<nblk, SCAN_T>>>(N);                     // 5
    k_fill<<<(E + T - 1) / T, T>>>(ei, E);               // 6
    k_agg1_l2<<<(4 * N + 255) / 256, 256>>>(b1, W2, N);  // 7
    k_agg2_final<<<(N + T - 1) / T, T>>>(b2, N, out);    // 8
}